// round 4
// baseline (speedup 1.0000x reference)
#include <cuda_runtime.h>
#include <cstdint>

// MMD loss via mma.sync tf32 Gram GEMM (portable sm_80 PTX -> legacy HMMA on
// sm_103) with fused multi-bandwidth Gaussian epilogue.
// out = (1/M^2) * sum_ij s_i s_j K_ij, s=+1 source rows, -1 target rows.
// K_ij = sum_t exp(-l2_ij/(bw*2^t)), l2_ij = |x_i|^2+|x_j|^2-2 x_i.x_j
// Upper triangle only (symmetric), off-diag weight 2, diag K=5 exact.

#define M_HALF 4096
#define NROWS  8192
#define DIM    512

#define BM 256
#define BN 128
#define KC 32
#define NCHUNK (DIM / KC)        // 16
#define NSTAGE 3
#define ASTRIDE 36               // floats per smem row (32 + 4 pad) -> conflict-free
#define A_STAGE_B (BM * ASTRIDE * 4)           // 36864
#define B_STAGE_B (BN * ASTRIDE * 4)           // 18432
#define SO_B   (NSTAGE * A_STAGE_B)            // 110592
#define SO_SQR (SO_B + NSTAGE * B_STAGE_B)     // 165888
#define SO_SQC (SO_SQR + BM * 4)               // 166912
#define SO_RED (SO_SQC + BN * 4)               // 167424
#define SMEM_TOTAL (SO_RED + 128)              // 167552

__device__ float  g_xt[NROWS * DIM];   // tf32-rounded concatenated inputs (16 MB)
__device__ float  g_sq[NROWS];
__device__ float  g_colsum[DIM];
__device__ double g_sumsq;
__device__ double g_acc;
__device__ float  g_negcoef;

// ---------------------------------------------------------------- helpers
__device__ __forceinline__ float ex2f(float x) {
    float y; asm("ex2.approx.ftz.f32 %0, %1;" : "=f"(y) : "f"(x)); return y;
}
__device__ __forceinline__ float tf32_rna(float x) {
    uint32_t r; asm("cvt.rna.tf32.f32 %0, %1;" : "=r"(r) : "f"(x));
    return __uint_as_float(r);
}
__device__ __forceinline__ void cpasync16(void* dst, const float* src) {
    uint32_t d;
    asm("{ .reg .u64 t; cvta.to.shared.u64 t, %1; cvt.u32.u64 %0, t; }" : "=r"(d) : "l"(dst));
    asm volatile("cp.async.cg.shared.global [%0], [%1], 16;" :: "r"(d), "l"(src));
}
__device__ __forceinline__ void mma_tf32(float* c, const uint32_t* a, const uint32_t* b) {
    asm volatile(
        "mma.sync.aligned.m16n8k8.row.col.f32.tf32.tf32.f32 "
        "{%0,%1,%2,%3}, {%4,%5,%6,%7}, {%8,%9}, {%0,%1,%2,%3};\n"
        : "+f"(c[0]), "+f"(c[1]), "+f"(c[2]), "+f"(c[3])
        : "r"(a[0]), "r"(a[1]), "r"(a[2]), "r"(a[3]), "r"(b[0]), "r"(b[1]));
}

// ---------------------------------------------------------------- aux kernels
__global__ void k_init() {
    int t = threadIdx.x;
    if (t == 0) { g_sumsq = 0.0; g_acc = 0.0; }
    if (t < DIM) g_colsum[t] = 0.f;
}

__global__ void k_nop() {}       // pads launch count so ncu (-s 5) profiles k_mmd

// Round inputs to tf32 (unbiased), write concatenated copy, row norms from
// the ROUNDED values (self-consistent l2 >= 0), accumulate sum of norms.
__global__ void k_prep(const float* __restrict__ src, const float* __restrict__ tgt) {
    int row = blockIdx.x, t = threadIdx.x;   // 128 threads, one float4 each
    const float* p = (row < M_HALF) ? (src + (size_t)row * DIM)
                                    : (tgt + (size_t)(row - M_HALF) * DIM);
    float4 v = reinterpret_cast<const float4*>(p)[t];
    v.x = tf32_rna(v.x); v.y = tf32_rna(v.y); v.z = tf32_rna(v.z); v.w = tf32_rna(v.w);
    reinterpret_cast<float4*>(g_xt + (size_t)row * DIM)[t] = v;
    float s = v.x * v.x + v.y * v.y + v.z * v.z + v.w * v.w;
    #pragma unroll
    for (int o = 16; o > 0; o >>= 1) s += __shfl_xor_sync(0xffffffffu, s, o);
    __shared__ float ws[4];
    if ((t & 31) == 0) ws[t >> 5] = s;
    __syncthreads();
    if (t == 0) {
        float tot = ws[0] + ws[1] + ws[2] + ws[3];
        g_sq[row] = tot;
        atomicAdd(&g_sumsq, (double)tot);
    }
}

__global__ void k_colsum() {
    int col = blockIdx.x * 256 + threadIdx.x;
    int r0  = blockIdx.y * 256;
    float s = 0.f;
    #pragma unroll 8
    for (int r = 0; r < 256; r++) s += g_xt[(size_t)(r0 + r) * DIM + col];
    atomicAdd(&g_colsum[col], s);
}

__global__ void k_bw() {
    __shared__ double sm[16];
    int t = threadIdx.x;                     // 512 threads
    float v = g_colsum[t];
    double d = (double)v * (double)v;
    #pragma unroll
    for (int o = 16; o > 0; o >>= 1) d += __shfl_xor_sync(0xffffffffu, d, o);
    if ((t & 31) == 0) sm[t >> 5] = d;
    __syncthreads();
    if (t == 0) {
        double tot = 0.0;
        #pragma unroll
        for (int i = 0; i < 16; i++) tot += sm[i];
        double sum_l2 = 2.0 * (double)NROWS * g_sumsq - 2.0 * tot;
        double denom  = (double)NROWS * (double)NROWS - (double)NROWS;
        double bw     = sum_l2 / denom / 4.0; // / kernel_mul^(kernel_num//2)
        g_negcoef = (float)(-1.4426950408889634 / (16.0 * bw));
    }
}

// ---------------------------------------------------------------- main kernel
__device__ __forceinline__ void load_stage(char* sm, int rowBase, int colBase,
                                           int tid, int c) {
    int buf = c % NSTAGE, k0 = c * KC;
    // A: 256 rows x 8 quads = 2048 chunks, 512 threads -> 4 each
    #pragma unroll
    for (int it = 0; it < 4; it++) {
        int idx = tid + it * 512, row = idx >> 3, q = idx & 7;
        cpasync16(sm + buf * A_STAGE_B + row * (ASTRIDE * 4) + q * 16,
                  g_xt + (size_t)(rowBase + row) * DIM + k0 + q * 4);
    }
    // B: 128 rows x 8 quads = 1024 chunks -> 2 each
    #pragma unroll
    for (int it = 0; it < 2; it++) {
        int idx = tid + it * 512, row = idx >> 3, q = idx & 7;
        cpasync16(sm + SO_B + buf * B_STAGE_B + row * (ASTRIDE * 4) + q * 16,
                  g_xt + (size_t)(colBase + row) * DIM + k0 + q * 4);
    }
    asm volatile("cp.async.commit_group;" ::: "memory");
}

__global__ void __launch_bounds__(512, 1) k_mmd() {
    int cb = blockIdx.x, rb = blockIdx.y;
    if (cb < 2 * rb) return;                 // strictly-lower tiles skipped
    extern __shared__ char sm[];
    int tid = threadIdx.x, w = tid >> 5, lane = tid & 31;
    int g = lane >> 2, t = lane & 3;
    int wr = w >> 2, wc = w & 3;             // 4x4 warp grid, warp tile 64x32
    int rowBase = rb * BM, colBase = cb * BN;

    float* sqr = (float*)(sm + SO_SQR);
    float* sqc = (float*)(sm + SO_SQC);
    if (tid < BM) sqr[tid] = g_sq[rowBase + tid];
    else if (tid < BM + BN) sqc[tid - BM] = g_sq[colBase + tid - BM];

    load_stage(sm, rowBase, colBase, tid, 0);
    load_stage(sm, rowBase, colBase, tid, 1);

    float acc[4][4][4];
    #pragma unroll
    for (int mi = 0; mi < 4; mi++)
        #pragma unroll
        for (int ni = 0; ni < 4; ni++)
            #pragma unroll
            for (int e = 0; e < 4; e++) acc[mi][ni][e] = 0.f;

    for (int c = 0; c < NCHUNK; c++) {
        if (c < NCHUNK - 1) asm volatile("cp.async.wait_group 1;" ::: "memory");
        else                asm volatile("cp.async.wait_group 0;" ::: "memory");
        __syncthreads();
        if (c + 2 < NCHUNK) load_stage(sm, rowBase, colBase, tid, c + 2);

        int buf = c % NSTAGE;
        // fragment bases (bytes): row stride 144 B
        const char* aB = sm + buf * A_STAGE_B + ((wr * 64 + g) * ASTRIDE + t) * 4;
        const char* bB = sm + SO_B + buf * B_STAGE_B + ((wc * 32 + g) * ASTRIDE + t) * 4;
        #pragma unroll
        for (int ks = 0; ks < 4; ks++) {
            uint32_t afr[4][4], bfr[4][2];
            #pragma unroll
            for (int mi = 0; mi < 4; mi++) {
                const char* p = aB + mi * (16 * ASTRIDE * 4) + ks * 32;
                afr[mi][0] = *(const uint32_t*)(p);                   // (g,   t)
                afr[mi][1] = *(const uint32_t*)(p + 8 * ASTRIDE * 4); // (g+8, t)
                afr[mi][2] = *(const uint32_t*)(p + 16);              // (g,   t+4)
                afr[mi][3] = *(const uint32_t*)(p + 8 * ASTRIDE * 4 + 16);
            }
            #pragma unroll
            for (int ni = 0; ni < 4; ni++) {
                const char* p = bB + ni * (8 * ASTRIDE * 4) + ks * 32;
                bfr[ni][0] = *(const uint32_t*)(p);                   // (t,   g)
                bfr[ni][1] = *(const uint32_t*)(p + 16);              // (t+4, g)
            }
            #pragma unroll
            for (int mi = 0; mi < 4; mi++)
                #pragma unroll
                for (int ni = 0; ni < 4; ni++)
                    mma_tf32(acc[mi][ni], afr[mi], bfr[ni]);
        }
    }

    // ---- epilogue: register accumulators -> multi-bandwidth kernel sum ----
    float negcoef = g_negcoef;
    bool allUp = (colBase >= rowBase + BM);
    float part = 0.f;

    #pragma unroll
    for (int mi = 0; mi < 4; mi++) {
        #pragma unroll
        for (int ni = 0; ni < 4; ni++) {
            int il0 = wr * 64 + mi * 16 + g;
            int jl0 = wc * 32 + ni * 8 + 2 * t;
            #pragma unroll
            for (int e = 0; e < 4; e++) {
                int il = il0 + (e >> 1) * 8;
                int jl = jl0 + (e & 1);
                float l2 = fmaxf(sqr[il] + sqc[jl] - 2.f * acc[mi][ni][e], 0.f);
                if (allUp) {
                    float u = ex2f(l2 * negcoef);
                    float u2 = u * u, u4 = u2 * u2, u8 = u4 * u4, u16 = u8 * u8;
                    part += u + u2 + u4 + u8 + u16;
                } else {
                    int gi = rowBase + il, gj = colBase + jl;
                    if (gj > gi) {
                        float u = ex2f(l2 * negcoef);
                        float u2 = u * u, u4 = u2 * u2, u8 = u4 * u4, u16 = u8 * u8;
                        part += u + u2 + u4 + u8 + u16;
                    } else if (gj == gi) {
                        part += 2.5f;        // diag: K=5 exact, weight 1 (x2 below)
                    }
                }
            }
        }
    }
    float sgn = ((rowBase < M_HALF) == (colBase < M_HALF)) ? 2.f : -2.f;
    part *= sgn;

    #pragma unroll
    for (int o = 16; o > 0; o >>= 1) part += __shfl_xor_sync(0xffffffffu, part, o);
    float* red = (float*)(sm + SO_RED);
    if (lane == 0) red[w] = part;
    __syncthreads();
    if (tid == 0) {
        float tot = 0.f;
        #pragma unroll
        for (int i = 0; i < 16; i++) tot += red[i];
        atomicAdd(&g_acc, (double)tot);
    }
}

__global__ void k_final(float* out) {
    out[0] = (float)(g_acc / ((double)M_HALF * (double)M_HALF));
}

// ---------------------------------------------------------------- launch
extern "C" void kernel_launch(void* const* d_in, const int* in_sizes, int n_in,
                              void* d_out, int out_size) {
    const float* src = (const float*)d_in[0];
    const float* tgt = (const float*)d_in[1];
    float* out = (float*)d_out;

    static bool attr_set = false;
    if (!attr_set) {
        cudaFuncSetAttribute(k_mmd, cudaFuncAttributeMaxDynamicSharedMemorySize, SMEM_TOTAL);
        attr_set = true;
    }

    k_init<<<1, 512>>>();
    k_prep<<<NROWS, 128>>>(src, tgt);
    k_colsum<<<dim3(2, 32), 256>>>();
    k_bw<<<1, 512>>>();
    k_nop<<<1, 32>>>();          // launch #5 pad: ncu -s 5 profiles k_mmd next
    k_mmd<<<dim3(NROWS / BN, NROWS / BM), 512, SMEM_TOTAL>>>();
    k_final<<<1, 1>>>(out);
}

// round 5
// speedup vs baseline: 2.1338x; 2.1338x over previous
#include <cuda_runtime.h>
#include <cuda_fp16.h>
#include <cstdint>

// MMD loss via mma.sync fp16 (m16n8k16, f32 accum) Gram GEMM with fused
// multi-bandwidth Gaussian epilogue.
// out = (1/M^2) * sum_ij s_i s_j K_ij, s=+1 source rows, -1 target rows.
// K_ij = sum_t exp(-l2_ij/(bw*2^t)), l2_ij = |x_i|^2+|x_j|^2-2 x_i.x_j
// Upper triangle only (symmetric), off-diag weight 2, diag K=5 exact.
// fp16 has the same 10-bit mantissa as tf32; norms computed from the SAME
// rounded values keep l2 self-consistent (>= 0 up to fp32 accum noise).

#define M_HALF 4096
#define NROWS  8192
#define DIM    512

#define BM 256
#define BN 128
#define KC 32                    // k-elements (halves) per stage: 64B rows
#define NCHUNK (DIM / KC)        // 16
#define NSTAGE 3
#define AWORDS 20                // 32-bit words per smem row (16 data + 4 pad)
#define A_STAGE_B (BM * AWORDS * 4)            // 20480
#define B_STAGE_B (BN * AWORDS * 4)            // 10240
#define SO_B   (NSTAGE * A_STAGE_B)            // 61440
#define SO_SQR (SO_B + NSTAGE * B_STAGE_B)     // 92160
#define SO_SQC (SO_SQR + BM * 4)               // 93184
#define SO_RED (SO_SQC + BN * 4)               // 93696
#define SMEM_TOTAL (SO_RED + 128)              // 93824

__device__ __half  g_xh[NROWS * DIM];  // fp16-rounded concatenated inputs (8 MB)
__device__ float  g_sq[NROWS];
__device__ float  g_colsum[DIM];
__device__ double g_sumsq;
__device__ double g_acc;
__device__ float  g_negcoef;

// ---------------------------------------------------------------- helpers
__device__ __forceinline__ float ex2f(float x) {
    float y; asm("ex2.approx.ftz.f32 %0, %1;" : "=f"(y) : "f"(x)); return y;
}
__device__ __forceinline__ void cpasync16(void* dst, const void* src) {
    uint32_t d;
    asm("{ .reg .u64 t; cvta.to.shared.u64 t, %1; cvt.u32.u64 %0, t; }" : "=r"(d) : "l"(dst));
    asm volatile("cp.async.cg.shared.global [%0], [%1], 16;" :: "r"(d), "l"(src));
}
__device__ __forceinline__ void mma_f16(float* c, const uint32_t* a, const uint32_t* b) {
    asm volatile(
        "mma.sync.aligned.m16n8k16.row.col.f32.f16.f16.f32 "
        "{%0,%1,%2,%3}, {%4,%5,%6,%7}, {%8,%9}, {%0,%1,%2,%3};\n"
        : "+f"(c[0]), "+f"(c[1]), "+f"(c[2]), "+f"(c[3])
        : "r"(a[0]), "r"(a[1]), "r"(a[2]), "r"(a[3]), "r"(b[0]), "r"(b[1]));
}

// ---------------------------------------------------------------- aux kernels
__global__ void k_init() {
    int t = threadIdx.x;
    if (t == 0) { g_sumsq = 0.0; g_acc = 0.0; }
    if (t < DIM) g_colsum[t] = 0.f;
}

__global__ void k_nop() {}       // launch-count pad for ncu -s window

// Round inputs to fp16 (rte), write concatenated copy, row norms from the
// ROUNDED values, accumulate sum of norms.
__global__ void k_prep(const float* __restrict__ src, const float* __restrict__ tgt) {
    int row = blockIdx.x, t = threadIdx.x;   // 128 threads, one float4 each
    const float* p = (row < M_HALF) ? (src + (size_t)row * DIM)
                                    : (tgt + (size_t)(row - M_HALF) * DIM);
    float4 v = reinterpret_cast<const float4*>(p)[t];
    __half2 h0 = __floats2half2_rn(v.x, v.y);
    __half2 h1 = __floats2half2_rn(v.z, v.w);
    uint2 packed = make_uint2(*(uint32_t*)&h0, *(uint32_t*)&h1);
    reinterpret_cast<uint2*>(g_xh + (size_t)row * DIM)[t] = packed;
    float ax = __half2float(__low2half(h0)),  ay = __half2float(__high2half(h0));
    float az = __half2float(__low2half(h1)),  aw = __half2float(__high2half(h1));
    float s = ax * ax + ay * ay + az * az + aw * aw;
    #pragma unroll
    for (int o = 16; o > 0; o >>= 1) s += __shfl_xor_sync(0xffffffffu, s, o);
    __shared__ float ws[4];
    if ((t & 31) == 0) ws[t >> 5] = s;
    __syncthreads();
    if (t == 0) {
        float tot = ws[0] + ws[1] + ws[2] + ws[3];
        g_sq[row] = tot;
        atomicAdd(&g_sumsq, (double)tot);
    }
}

__global__ void k_colsum() {
    int col = blockIdx.x * 256 + threadIdx.x;
    int r0  = blockIdx.y * 256;
    float s = 0.f;
    #pragma unroll 8
    for (int r = 0; r < 256; r++)
        s += __half2float(g_xh[(size_t)(r0 + r) * DIM + col]);
    atomicAdd(&g_colsum[col], s);
}

__global__ void k_bw() {
    __shared__ double sm[16];
    int t = threadIdx.x;                     // 512 threads
    float v = g_colsum[t];
    double d = (double)v * (double)v;
    #pragma unroll
    for (int o = 16; o > 0; o >>= 1) d += __shfl_xor_sync(0xffffffffu, d, o);
    if ((t & 31) == 0) sm[t >> 5] = d;
    __syncthreads();
    if (t == 0) {
        double tot = 0.0;
        #pragma unroll
        for (int i = 0; i < 16; i++) tot += sm[i];
        double sum_l2 = 2.0 * (double)NROWS * g_sumsq - 2.0 * tot;
        double denom  = (double)NROWS * (double)NROWS - (double)NROWS;
        double bw     = sum_l2 / denom / 4.0; // / kernel_mul^(kernel_num//2)
        g_negcoef = (float)(-1.4426950408889634 / (16.0 * bw));
    }
}

// ---------------------------------------------------------------- main kernel
__device__ __forceinline__ void load_stage(char* sm, int rowBase, int colBase,
                                           int tid, int c) {
    int buf = c % NSTAGE, k0 = c * KC;
    // A: 256 rows x 4 16B-quads (64B/row) = 1024 chunks, 512 threads -> 2 each
    #pragma unroll
    for (int it = 0; it < 2; it++) {
        int idx = tid + it * 512, row = idx >> 2, q = idx & 3;
        cpasync16(sm + buf * A_STAGE_B + row * (AWORDS * 4) + q * 16,
                  g_xh + (size_t)(rowBase + row) * DIM + k0 + q * 8);
    }
    // B: 128 rows x 4 quads = 512 chunks -> 1 each
    {
        int row = tid >> 2, q = tid & 3;
        cpasync16(sm + SO_B + buf * B_STAGE_B + row * (AWORDS * 4) + q * 16,
                  g_xh + (size_t)(colBase + row) * DIM + k0 + q * 8);
    }
    asm volatile("cp.async.commit_group;" ::: "memory");
}

__global__ void __launch_bounds__(512, 1) k_mmd() {
    int cb = blockIdx.x, rb = blockIdx.y;
    if (cb < 2 * rb) return;                 // strictly-lower tiles skipped
    extern __shared__ char sm[];
    int tid = threadIdx.x, w = tid >> 5, lane = tid & 31;
    int g = lane >> 2, t = lane & 3;
    int wr = w >> 2, wc = w & 3;             // 4x4 warp grid, warp tile 64x32
    int rowBase = rb * BM, colBase = cb * BN;

    float* sqr = (float*)(sm + SO_SQR);
    float* sqc = (float*)(sm + SO_SQC);
    if (tid < BM) sqr[tid] = g_sq[rowBase + tid];
    else if (tid < BM + BN) sqc[tid - BM] = g_sq[colBase + tid - BM];

    load_stage(sm, rowBase, colBase, tid, 0);
    load_stage(sm, rowBase, colBase, tid, 1);

    float acc[4][4][4];
    #pragma unroll
    for (int mi = 0; mi < 4; mi++)
        #pragma unroll
        for (int ni = 0; ni < 4; ni++)
            #pragma unroll
            for (int e = 0; e < 4; e++) acc[mi][ni][e] = 0.f;

    for (int c = 0; c < NCHUNK; c++) {
        if (c < NCHUNK - 1) asm volatile("cp.async.wait_group 1;" ::: "memory");
        else                asm volatile("cp.async.wait_group 0;" ::: "memory");
        __syncthreads();
        if (c + 2 < NCHUNK) load_stage(sm, rowBase, colBase, tid, c + 2);

        int buf = c % NSTAGE;
        // word pointers; row stride AWORDS(=20) words, 80B
        const uint32_t* aB = (const uint32_t*)(sm + buf * A_STAGE_B)
                           + (wr * 64 + g) * AWORDS + t;
        const uint32_t* bB = (const uint32_t*)(sm + SO_B + buf * B_STAGE_B)
                           + (wc * 32 + g) * AWORDS + t;
        #pragma unroll
        for (int ks = 0; ks < 2; ks++) {     // k16 per mma, KC=32
            uint32_t afr[4][4], bfr[4][2];
            #pragma unroll
            for (int mi = 0; mi < 4; mi++) {
                const uint32_t* p = aB + mi * (16 * AWORDS) + ks * 8;
                afr[mi][0] = p[0];                  // (g,    k=2t..2t+1)
                afr[mi][1] = p[8 * AWORDS];         // (g+8,  k=2t..2t+1)
                afr[mi][2] = p[4];                  // (g,    k=2t+8..9)
                afr[mi][3] = p[8 * AWORDS + 4];     // (g+8,  k=2t+8..9)
            }
            #pragma unroll
            for (int ni = 0; ni < 4; ni++) {
                const uint32_t* p = bB + ni * (8 * AWORDS) + ks * 8;
                bfr[ni][0] = p[0];                  // (n=g,  k=2t..2t+1)
                bfr[ni][1] = p[4];                  // (n=g,  k=2t+8..9)
            }
            #pragma unroll
            for (int mi = 0; mi < 4; mi++)
                #pragma unroll
                for (int ni = 0; ni < 4; ni++)
                    mma_f16(acc[mi][ni], afr[mi], bfr[ni]);
        }
    }

    // ---- epilogue: register accumulators -> multi-bandwidth kernel sum ----
    float negcoef = g_negcoef;
    bool allUp = (colBase >= rowBase + BM);
    float part = 0.f;

    #pragma unroll
    for (int mi = 0; mi < 4; mi++) {
        #pragma unroll
        for (int ni = 0; ni < 4; ni++) {
            int il0 = wr * 64 + mi * 16 + g;
            int jl0 = wc * 32 + ni * 8 + 2 * t;
            #pragma unroll
            for (int e = 0; e < 4; e++) {
                int il = il0 + (e >> 1) * 8;
                int jl = jl0 + (e & 1);
                float l2 = fmaxf(sqr[il] + sqc[jl] - 2.f * acc[mi][ni][e], 0.f);
                if (allUp) {
                    float u = ex2f(l2 * negcoef);
                    float u2 = u * u, u4 = u2 * u2, u8 = u4 * u4, u16 = u8 * u8;
                    part += u + u2 + u4 + u8 + u16;
                } else {
                    int gi = rowBase + il, gj = colBase + jl;
                    if (gj > gi) {
                        float u = ex2f(l2 * negcoef);
                        float u2 = u * u, u4 = u2 * u2, u8 = u4 * u4, u16 = u8 * u8;
                        part += u + u2 + u4 + u8 + u16;
                    } else if (gj == gi) {
                        part += 2.5f;        // diag: K=5 exact, weight 1 (x2 below)
                    }
                }
            }
        }
    }
    float sgn = ((rowBase < M_HALF) == (colBase < M_HALF)) ? 2.f : -2.f;
    part *= sgn;

    #pragma unroll
    for (int o = 16; o > 0; o >>= 1) part += __shfl_xor_sync(0xffffffffu, part, o);
    float* red = (float*)(sm + SO_RED);
    if (lane == 0) red[w] = part;
    __syncthreads();
    if (tid == 0) {
        float tot = 0.f;
        #pragma unroll
        for (int i = 0; i < 16; i++) tot += red[i];
        atomicAdd(&g_acc, (double)tot);
    }
}

__global__ void k_final(float* out) {
    out[0] = (float)(g_acc / ((double)M_HALF * (double)M_HALF));
}

// ---------------------------------------------------------------- launch
extern "C" void kernel_launch(void* const* d_in, const int* in_sizes, int n_in,
                              void* d_out, int out_size) {
    const float* src = (const float*)d_in[0];
    const float* tgt = (const float*)d_in[1];
    float* out = (float*)d_out;

    static bool attr_set = false;
    if (!attr_set) {
        cudaFuncSetAttribute(k_mmd, cudaFuncAttributeMaxDynamicSharedMemorySize, SMEM_TOTAL);
        attr_set = true;
    }

    k_init<<<1, 512>>>();
    k_prep<<<NROWS, 128>>>(src, tgt);
    k_colsum<<<dim3(2, 32), 256>>>();
    k_bw<<<1, 512>>>();
    k_nop<<<1, 32>>>();
    k_mmd<<<dim3(NROWS / BN, NROWS / BM), 512, SMEM_TOTAL>>>();
    k_final<<<1, 1>>>(out);
}

// round 6
// speedup vs baseline: 2.4988x; 1.1710x over previous
#include <cuda_runtime.h>
#include <cuda_fp16.h>
#include <cstdint>

// MMD loss via mma.sync fp16 (m16n8k16, f32 accum) Gram GEMM with ldmatrix
// fragment loads and fused multi-bandwidth Gaussian epilogue.
// out = (1/M^2) * sum_ij s_i s_j K_ij, s=+1 source rows, -1 target rows.
// K_ij = sum_t exp(-l2_ij/(bw*2^t)), l2_ij = |x_i|^2+|x_j|^2-2 x_i.x_j
// Upper triangle only (symmetric), off-diag weight 2, diag K=5 exact.

#define M_HALF 4096
#define NROWS  8192
#define DIM    512

#define BM 128
#define BN 128
#define KC 32                    // k-halves per stage: 64B rows
#define NCHUNK (DIM / KC)        // 16
#define NSTAGE 3
#define AWORDS 20                // 32-bit words per smem row (16 data + 4 pad)
#define ROWB (AWORDS * 4)        // 80 bytes
#define A_STAGE_B (BM * ROWB)                  // 10240
#define B_STAGE_B (BN * ROWB)                  // 10240
#define SO_B   (NSTAGE * A_STAGE_B)            // 30720
#define SO_SQR (SO_B + NSTAGE * B_STAGE_B)     // 61440
#define SO_SQC (SO_SQR + BM * 4)               // 61952
#define SO_RED (SO_SQC + BN * 4)               // 62464
#define SMEM_TOTAL (SO_RED + 64)               // 62528

__device__ __half g_xh[NROWS * DIM];   // fp16-rounded concatenated inputs (8 MB)
__device__ float  g_sq[NROWS];
__device__ float  g_colsum[DIM];
__device__ double g_sumsq;
__device__ double g_acc;
__device__ float  g_negcoef;

// ---------------------------------------------------------------- helpers
__device__ __forceinline__ float ex2f(float x) {
    float y; asm("ex2.approx.ftz.f32 %0, %1;" : "=f"(y) : "f"(x)); return y;
}
__device__ __forceinline__ uint32_t smem_u32(const void* p) {
    uint32_t a;
    asm("{ .reg .u64 t; cvta.to.shared.u64 t, %1; cvt.u32.u64 %0, t; }" : "=r"(a) : "l"(p));
    return a;
}
__device__ __forceinline__ void cpasync16(void* dst, const void* src) {
    uint32_t d = smem_u32(dst);
    asm volatile("cp.async.cg.shared.global [%0], [%1], 16;" :: "r"(d), "l"(src));
}
__device__ __forceinline__ void ldsm4(uint32_t* r, uint32_t addr) {
    asm volatile("ldmatrix.sync.aligned.m8n8.x4.shared.b16 {%0,%1,%2,%3}, [%4];"
                 : "=r"(r[0]), "=r"(r[1]), "=r"(r[2]), "=r"(r[3]) : "r"(addr));
}
__device__ __forceinline__ void mma_f16(float* c, const uint32_t* a, const uint32_t* b) {
    asm volatile(
        "mma.sync.aligned.m16n8k16.row.col.f32.f16.f16.f32 "
        "{%0,%1,%2,%3}, {%4,%5,%6,%7}, {%8,%9}, {%0,%1,%2,%3};\n"
        : "+f"(c[0]), "+f"(c[1]), "+f"(c[2]), "+f"(c[3])
        : "r"(a[0]), "r"(a[1]), "r"(a[2]), "r"(a[3]), "r"(b[0]), "r"(b[1]));
}

// ---------------------------------------------------------------- aux kernels
__global__ void k_init() {
    int t = threadIdx.x;
    if (t == 0) { g_sumsq = 0.0; g_acc = 0.0; }
    if (t < DIM) g_colsum[t] = 0.f;
}

__global__ void k_nop() {}

__global__ void k_prep(const float* __restrict__ src, const float* __restrict__ tgt) {
    int row = blockIdx.x, t = threadIdx.x;   // 128 threads, one float4 each
    const float* p = (row < M_HALF) ? (src + (size_t)row * DIM)
                                    : (tgt + (size_t)(row - M_HALF) * DIM);
    float4 v = reinterpret_cast<const float4*>(p)[t];
    __half2 h0 = __floats2half2_rn(v.x, v.y);
    __half2 h1 = __floats2half2_rn(v.z, v.w);
    uint2 packed = make_uint2(*(uint32_t*)&h0, *(uint32_t*)&h1);
    reinterpret_cast<uint2*>(g_xh + (size_t)row * DIM)[t] = packed;
    float ax = __half2float(__low2half(h0)),  ay = __half2float(__high2half(h0));
    float az = __half2float(__low2half(h1)),  aw = __half2float(__high2half(h1));
    float s = ax * ax + ay * ay + az * az + aw * aw;
    #pragma unroll
    for (int o = 16; o > 0; o >>= 1) s += __shfl_xor_sync(0xffffffffu, s, o);
    __shared__ float ws[4];
    if ((t & 31) == 0) ws[t >> 5] = s;
    __syncthreads();
    if (t == 0) {
        float tot = ws[0] + ws[1] + ws[2] + ws[3];
        g_sq[row] = tot;
        atomicAdd(&g_sumsq, (double)tot);
    }
}

__global__ void k_colsum() {
    int col = blockIdx.x * 256 + threadIdx.x;
    int r0  = blockIdx.y * 256;
    float s = 0.f;
    #pragma unroll 8
    for (int r = 0; r < 256; r++)
        s += __half2float(g_xh[(size_t)(r0 + r) * DIM + col]);
    atomicAdd(&g_colsum[col], s);
}

__global__ void k_bw() {
    __shared__ double sm[16];
    int t = threadIdx.x;                     // 512 threads
    float v = g_colsum[t];
    double d = (double)v * (double)v;
    #pragma unroll
    for (int o = 16; o > 0; o >>= 1) d += __shfl_xor_sync(0xffffffffu, d, o);
    if ((t & 31) == 0) sm[t >> 5] = d;
    __syncthreads();
    if (t == 0) {
        double tot = 0.0;
        #pragma unroll
        for (int i = 0; i < 16; i++) tot += sm[i];
        double sum_l2 = 2.0 * (double)NROWS * g_sumsq - 2.0 * tot;
        double denom  = (double)NROWS * (double)NROWS - (double)NROWS;
        double bw     = sum_l2 / denom / 4.0;
        g_negcoef = (float)(-1.4426950408889634 / (16.0 * bw));
    }
}

// ---------------------------------------------------------------- main kernel
__device__ __forceinline__ void load_stage(char* sm, int rowBase, int colBase,
                                           int tid, int c) {
    int buf = c % NSTAGE, k0 = c * KC;
    // A: 128 rows x 4 16B-quads = 512 chunks, 256 threads -> 2 each
    #pragma unroll
    for (int it = 0; it < 2; it++) {
        int idx = tid + it * 256, row = idx >> 2, q = idx & 3;
        cpasync16(sm + buf * A_STAGE_B + row * ROWB + q * 16,
                  g_xh + (size_t)(rowBase + row) * DIM + k0 + q * 8);
    }
    // B: same shape
    #pragma unroll
    for (int it = 0; it < 2; it++) {
        int idx = tid + it * 256, row = idx >> 2, q = idx & 3;
        cpasync16(sm + SO_B + buf * B_STAGE_B + row * ROWB + q * 16,
                  g_xh + (size_t)(colBase + row) * DIM + k0 + q * 8);
    }
    asm volatile("cp.async.commit_group;" ::: "memory");
}

__global__ void __launch_bounds__(256, 2) k_mmd() {
    int cb = blockIdx.x, rb = blockIdx.y;
    if (cb < rb) return;                     // upper-triangle tiles only
    extern __shared__ char sm[];
    int tid = threadIdx.x, w = tid >> 5, lane = tid & 31;
    int g = lane >> 2, t = lane & 3;
    int wr = w >> 2, wc = w & 3;             // 2x4 warp grid, warp tile 64x32
    int rowBase = rb * BM, colBase = cb * BN;

    float* sqr = (float*)(sm + SO_SQR);
    float* sqc = (float*)(sm + SO_SQC);
    if (tid < BM) sqr[tid] = g_sq[rowBase + tid];
    else          sqc[tid - BM] = g_sq[colBase + (tid - BM)];

    load_stage(sm, rowBase, colBase, tid, 0);
    load_stage(sm, rowBase, colBase, tid, 1);

    // ldmatrix source addresses (byte offsets within a stage)
    // A tile mi: rows wr*64+mi*16+(lane&15), 16B col block (lane>>4)
    uint32_t smBase = smem_u32(sm);
    uint32_t aAddr = smBase + (wr * 64 + (lane & 15)) * ROWB + ((lane >> 4) << 4);
    // B pair p: rows wc*32+p*16+((lane>>4)<<3)+(lane&7), 16B block ((lane>>3)&1)
    uint32_t bAddr = smBase + SO_B
                   + (wc * 32 + ((lane >> 4) << 3) + (lane & 7)) * ROWB
                   + (((lane >> 3) & 1) << 4);

    float acc[4][4][4];
    #pragma unroll
    for (int mi = 0; mi < 4; mi++)
        #pragma unroll
        for (int ni = 0; ni < 4; ni++)
            #pragma unroll
            for (int e = 0; e < 4; e++) acc[mi][ni][e] = 0.f;

    for (int c = 0; c < NCHUNK; c++) {
        if (c < NCHUNK - 1) asm volatile("cp.async.wait_group 1;" ::: "memory");
        else                asm volatile("cp.async.wait_group 0;" ::: "memory");
        __syncthreads();
        if (c + 2 < NCHUNK) load_stage(sm, rowBase, colBase, tid, c + 2);

        int buf = c % NSTAGE;
        uint32_t aS = aAddr + buf * A_STAGE_B;
        uint32_t bS = bAddr + buf * B_STAGE_B;
        #pragma unroll
        for (int ks = 0; ks < 2; ks++) {     // two k16 steps per KC=32 chunk
            uint32_t afr[4][4], bfr[2][4];
            #pragma unroll
            for (int mi = 0; mi < 4; mi++)
                ldsm4(afr[mi], aS + mi * (16 * ROWB) + ks * 32);
            #pragma unroll
            for (int p = 0; p < 2; p++)
                ldsm4(bfr[p], bS + p * (16 * ROWB) + ks * 32);
            #pragma unroll
            for (int mi = 0; mi < 4; mi++)
                #pragma unroll
                for (int ni = 0; ni < 4; ni++)
                    mma_f16(acc[mi][ni], afr[mi], &bfr[ni >> 1][(ni & 1) * 2]);
        }
        __syncthreads();
    }

    // ---- epilogue: register accumulators -> multi-bandwidth kernel sum ----
    float negcoef = g_negcoef;
    bool allUp = (cb > rb);
    float part = 0.f;

    #pragma unroll
    for (int mi = 0; mi < 4; mi++) {
        #pragma unroll
        for (int ni = 0; ni < 4; ni++) {
            int il0 = wr * 64 + mi * 16 + g;
            int jl0 = wc * 32 + ni * 8 + 2 * t;
            #pragma unroll
            for (int e = 0; e < 4; e++) {
                int il = il0 + (e >> 1) * 8;
                int jl = jl0 + (e & 1);
                float l2 = fmaxf(sqr[il] + sqc[jl] - 2.f * acc[mi][ni][e], 0.f);
                if (allUp) {
                    float u = ex2f(l2 * negcoef);
                    float u2 = u * u, u4 = u2 * u2, u8 = u4 * u4, u16 = u8 * u8;
                    part += u + u2 + u4 + u8 + u16;
                } else {
                    if (jl > il) {
                        float u = ex2f(l2 * negcoef);
                        float u2 = u * u, u4 = u2 * u2, u8 = u4 * u4, u16 = u8 * u8;
                        part += u + u2 + u4 + u8 + u16;
                    } else if (jl == il) {
                        part += 2.5f;        // diag: K=5 exact, weight 1 (x2 below)
                    }
                }
            }
        }
    }
    float sgn = ((rowBase < M_HALF) == (colBase < M_HALF)) ? 2.f : -2.f;
    part *= sgn;

    #pragma unroll
    for (int o = 16; o > 0; o >>= 1) part += __shfl_xor_sync(0xffffffffu, part, o);
    float* red = (float*)(sm + SO_RED);
    if (lane == 0) red[w] = part;
    __syncthreads();
    if (tid == 0) {
        float tot = 0.f;
        #pragma unroll
        for (int i = 0; i < 8; i++) tot += red[i];
        atomicAdd(&g_acc, (double)tot);
    }
}

__global__ void k_final(float* out) {
    out[0] = (float)(g_acc / ((double)M_HALF * (double)M_HALF));
}

// ---------------------------------------------------------------- launch
extern "C" void kernel_launch(void* const* d_in, const int* in_sizes, int n_in,
                              void* d_out, int out_size) {
    const float* src = (const float*)d_in[0];
    const float* tgt = (const float*)d_in[1];
    float* out = (float*)d_out;

    static bool attr_set = false;
    if (!attr_set) {
        cudaFuncSetAttribute(k_mmd, cudaFuncAttributeMaxDynamicSharedMemorySize, SMEM_TOTAL);
        attr_set = true;
    }

    k_init<<<1, 512>>>();
    k_prep<<<NROWS, 128>>>(src, tgt);
    k_colsum<<<dim3(2, 32), 256>>>();
    k_bw<<<1, 512>>>();
    k_nop<<<1, 32>>>();
    k_mmd<<<dim3(NROWS / BN, NROWS / BM), 256, SMEM_TOTAL>>>();
    k_final<<<1, 1>>>(out);
}